// round 1
// baseline (speedup 1.0000x reference)
#include <cuda_runtime.h>
#include <math.h>

// Problem constants
#define Bn  8
#define Cin 1024
#define Sn  2048
#define KD  512
#define OD  1024

// Scratch (device globals — no allocation allowed in kernel_launch)
__device__ float g_q [(size_t)Bn * KD * Sn];   //  33.5 MB  (B, KD, S)
__device__ float g_k [(size_t)Bn * KD * Sn];   //  33.5 MB  (B, KD, S)
__device__ float g_v [(size_t)Bn * OD * Sn];   //  67   MB  (B, OD, S)
__device__ float g_sc[(size_t)Bn * Sn * Sn];   // 134   MB  (B, S, S)

// ---------------------------------------------------------------------------
// Generic 128x128x16 fp32 tiled GEMM, 256 threads, 8x8 per-thread micro-tile.
//   Logical op: C[m,n] = alpha * sum_k A[m,k] * B[k,n]  (+ bias[m])
//   A_KMAJOR: A stored as (K x M) row-major (lda = M), else (M x K) (lda = K)
//   B_KMAJOR: B stored as (K x N) row-major (ldb = N), else (N x K) (ldb = K)
// Batched over blockIdx.z via byte-free element strides sA/sB/sC (sA=0 => shared A).
// All M,N multiples of 128 and K multiples of 16 in this problem — no bounds checks.
// ---------------------------------------------------------------------------
template<bool A_KMAJOR, bool B_KMAJOR, bool HAS_BIAS>
__global__ __launch_bounds__(256)
void gemm128(const float* __restrict__ A, const float* __restrict__ B,
             const float* __restrict__ bias, float* __restrict__ C,
             int M, int N, int K,
             size_t sA, size_t sB, size_t sC, float alpha)
{
    __shared__ float As[16][132];
    __shared__ float Bs[16][132];

    A += (size_t)blockIdx.z * sA;
    B += (size_t)blockIdx.z * sB;
    C += (size_t)blockIdx.z * sC;

    const int tid = threadIdx.x;
    const int tx  = tid & 15;      // 0..15 -> n
    const int ty  = tid >> 4;      // 0..15 -> m
    const int m0  = blockIdx.y * 128;
    const int n0  = blockIdx.x * 128;

    float acc[8][8];
#pragma unroll
    for (int i = 0; i < 8; i++)
#pragma unroll
        for (int j = 0; j < 8; j++) acc[i][j] = 0.0f;

    for (int k0 = 0; k0 < K; k0 += 16) {
        // ---- load A tile (128m x 16k) into As[k][m] ----
#pragma unroll
        for (int it = 0; it < 2; it++) {
            const int slot = tid + it * 256;           // 0..511 float4 slots
            if (A_KMAJOR) {
                const int r = slot >> 5;               // k row 0..15
                const int c = (slot & 31) << 2;        // m col 0..124 step 4
                float4 va = *(const float4*)(A + (size_t)(k0 + r) * M + m0 + c);
                *(float4*)&As[r][c] = va;
            } else {
                const int r = slot >> 2;               // m row 0..127
                const int c = (slot & 3) << 2;         // k col 0..12 step 4
                float4 va = *(const float4*)(A + (size_t)(m0 + r) * K + k0 + c);
                As[c + 0][r] = va.x;
                As[c + 1][r] = va.y;
                As[c + 2][r] = va.z;
                As[c + 3][r] = va.w;
            }
        }
        // ---- load B tile (16k x 128n) into Bs[k][n] ----
#pragma unroll
        for (int it = 0; it < 2; it++) {
            const int slot = tid + it * 256;
            if (B_KMAJOR) {
                const int r = slot >> 5;
                const int c = (slot & 31) << 2;
                float4 vb = *(const float4*)(B + (size_t)(k0 + r) * N + n0 + c);
                *(float4*)&Bs[r][c] = vb;
            } else {
                const int r = slot >> 2;               // n row 0..127
                const int c = (slot & 3) << 2;         // k col
                float4 vb = *(const float4*)(B + (size_t)(n0 + r) * K + k0 + c);
                Bs[c + 0][r] = vb.x;
                Bs[c + 1][r] = vb.y;
                Bs[c + 2][r] = vb.z;
                Bs[c + 3][r] = vb.w;
            }
        }
        __syncthreads();

#pragma unroll
        for (int kk = 0; kk < 16; kk++) {
            float a[8], b[8];
            *(float4*)&a[0] = *(const float4*)&As[kk][ty * 8];
            *(float4*)&a[4] = *(const float4*)&As[kk][ty * 8 + 4];
            *(float4*)&b[0] = *(const float4*)&Bs[kk][tx * 8];
            *(float4*)&b[4] = *(const float4*)&Bs[kk][tx * 8 + 4];
#pragma unroll
            for (int i = 0; i < 8; i++)
#pragma unroll
                for (int j = 0; j < 8; j++)
                    acc[i][j] = fmaf(a[i], b[j], acc[i][j]);
        }
        __syncthreads();
    }

    // ---- epilogue ----
#pragma unroll
    for (int i = 0; i < 8; i++) {
        const int m  = m0 + ty * 8 + i;
        const float bb = HAS_BIAS ? bias[m] : 0.0f;
        float* crow = C + (size_t)m * N + n0 + tx * 8;
#pragma unroll
        for (int j = 0; j < 8; j += 4) {
            float4 o;
            o.x = acc[i][j + 0] * alpha + bb;
            o.y = acc[i][j + 1] * alpha + bb;
            o.z = acc[i][j + 2] * alpha + bb;
            o.w = acc[i][j + 3] * alpha + bb;
            *(float4*)(crow + j) = o;
        }
    }
}

// ---------------------------------------------------------------------------
// Row softmax over 2048 elements, one block (256 threads) per row, in place.
// ---------------------------------------------------------------------------
__global__ __launch_bounds__(256)
void softmax2048(float* __restrict__ sc)
{
    float4* pv = (float4*)(sc + (size_t)blockIdx.x * 2048);
    const int tid = threadIdx.x;

    float4 v0 = pv[tid];
    float4 v1 = pv[tid + 256];

    __shared__ float red[8];

    // --- row max ---
    float m = fmaxf(fmaxf(fmaxf(v0.x, v0.y), fmaxf(v0.z, v0.w)),
                    fmaxf(fmaxf(v1.x, v1.y), fmaxf(v1.z, v1.w)));
#pragma unroll
    for (int o = 16; o; o >>= 1) m = fmaxf(m, __shfl_xor_sync(0xffffffffu, m, o));
    if ((tid & 31) == 0) red[tid >> 5] = m;
    __syncthreads();
    float rowmax = red[0];
#pragma unroll
    for (int i = 1; i < 8; i++) rowmax = fmaxf(rowmax, red[i]);
    __syncthreads();   // everyone done reading red before reuse

    // --- exp + row sum ---
    v0.x = __expf(v0.x - rowmax); v0.y = __expf(v0.y - rowmax);
    v0.z = __expf(v0.z - rowmax); v0.w = __expf(v0.w - rowmax);
    v1.x = __expf(v1.x - rowmax); v1.y = __expf(v1.y - rowmax);
    v1.z = __expf(v1.z - rowmax); v1.w = __expf(v1.w - rowmax);

    float s = (v0.x + v0.y + v0.z + v0.w) + (v1.x + v1.y + v1.z + v1.w);
#pragma unroll
    for (int o = 16; o; o >>= 1) s += __shfl_xor_sync(0xffffffffu, s, o);
    if ((tid & 31) == 0) red[tid >> 5] = s;
    __syncthreads();
    float tot = red[0];
#pragma unroll
    for (int i = 1; i < 8; i++) tot += red[i];
    const float inv = 1.0f / tot;

    v0.x *= inv; v0.y *= inv; v0.z *= inv; v0.w *= inv;
    v1.x *= inv; v1.y *= inv; v1.z *= inv; v1.w *= inv;
    pv[tid]       = v0;
    pv[tid + 256] = v1;
}

// ---------------------------------------------------------------------------
extern "C" void kernel_launch(void* const* d_in, const int* in_sizes, int n_in,
                              void* d_out, int out_size)
{
    (void)in_sizes; (void)n_in; (void)out_size;
    const float* x  = (const float*)d_in[0];
    const float* wq = (const float*)d_in[1];
    const float* bq = (const float*)d_in[2];
    const float* wk = (const float*)d_in[3];
    const float* bk = (const float*)d_in[4];
    const float* wv = (const float*)d_in[5];
    const float* bv = (const float*)d_in[6];
    float* out = (float*)d_out;

    float *pq, *pk, *pv, *psc;
    cudaGetSymbolAddress((void**)&pq,  g_q);
    cudaGetSymbolAddress((void**)&pk,  g_k);
    cudaGetSymbolAddress((void**)&pv,  g_v);
    cudaGetSymbolAddress((void**)&psc, g_sc);

    const dim3 blk(256);
    const size_t sx  = (size_t)Cin * Sn;   // x batch stride
    const size_t sq  = (size_t)KD  * Sn;
    const size_t sv  = (size_t)OD  * Sn;
    const size_t ssc = (size_t)Sn  * Sn;

    // Phase 1: q/k/v = W @ x + b      (out layout: B x ch x S)
    gemm128<false, true, true><<<dim3(Sn / 128, KD / 128, Bn), blk>>>(
        wq, x, bq, pq, KD, Sn, Cin, 0, sx, sq, 1.0f);
    gemm128<false, true, true><<<dim3(Sn / 128, KD / 128, Bn), blk>>>(
        wk, x, bk, pk, KD, Sn, Cin, 0, sx, sq, 1.0f);
    gemm128<false, true, true><<<dim3(Sn / 128, OD / 128, Bn), blk>>>(
        wv, x, bv, pv, OD, Sn, Cin, 0, sx, sv, 1.0f);

    // Phase 2: scores[s,t] = (1/sqrt(KD)) * sum_kd q[kd,s] * k[kd,t]   (TN)
    const float inv_sqrt_kd = 0.04419417382415922f;  // 1/sqrt(512)
    gemm128<true, true, false><<<dim3(Sn / 128, Sn / 128, Bn), blk>>>(
        pq, pk, nullptr, psc, Sn, Sn, KD, sq, sq, ssc, inv_sqrt_kd);

    // Phase 3: row softmax over t (in place)
    softmax2048<<<Bn * Sn, 256>>>(psc);

    // Phase 4: out[o,s] = sum_t v[o,t] * attn[s,t]   (NT), writes (B,O,S) directly
    gemm128<false, false, false><<<dim3(Sn / 128, OD / 128, Bn), blk>>>(
        pv, psc, nullptr, out, OD, Sn, Sn, sv, ssc, sv, 1.0f);
}

// round 3
// speedup vs baseline: 2.9441x; 2.9441x over previous
#include <cuda_runtime.h>
#include <cuda_bf16.h>
#include <cstdint>
#include <math.h>

#define Bn  8
#define Cin 1024
#define Sn  2048
#define KD  512
#define OD  1024

// ---------------- scratch (device globals; no runtime allocation) ----------
__device__ uint32_t g_xT[(size_t)Bn * Sn * Cin];   // xT packed hi/lo (B,S,C)
__device__ uint32_t g_wq[(size_t)KD * Cin];
__device__ uint32_t g_wk[(size_t)KD * Cin];
__device__ uint32_t g_wv[(size_t)OD * Cin];
__device__ uint32_t g_qp[(size_t)Bn * Sn * KD];    // q packed (B,S,KD)
__device__ uint32_t g_kp[(size_t)Bn * Sn * KD];    // k packed (B,S,KD)
__device__ uint32_t g_vp[(size_t)Bn * OD * Sn];    // v packed (B,OD,S)
__device__ float    g_sc[(size_t)Bn * Sn * Sn];    // scores fp32 -> attn packed

// ---------------- helpers ---------------------------------------------------
__device__ __forceinline__ uint32_t smem_u32(const void* p) {
    uint32_t a;
    asm("{ .reg .u64 t; cvta.to.shared.u64 t, %1; cvt.u32.u64 %0, t; }" : "=r"(a) : "l"(p));
    return a;
}

__device__ __forceinline__ uint32_t pack_hl(float v) {
    __nv_bfloat16 h = __float2bfloat16(v);
    float hf = __bfloat162float(h);
    __nv_bfloat16 l = __float2bfloat16(v - hf);
    return (uint32_t)__bfloat16_as_ushort(h) | ((uint32_t)__bfloat16_as_ushort(l) << 16);
}

#define LDSM_X4(r0, r1, r2, r3, addr) \
    asm volatile("ldmatrix.sync.aligned.m8n8.x4.shared.b16 {%0,%1,%2,%3}, [%4];" \
                 : "=r"(r0), "=r"(r1), "=r"(r2), "=r"(r3) : "r"(addr))

__device__ __forceinline__ void mma16816(float* d, const uint32_t* a, const uint32_t* b) {
    asm volatile(
        "mma.sync.aligned.m16n8k16.row.col.f32.bf16.bf16.f32 "
        "{%0,%1,%2,%3}, {%4,%5,%6,%7}, {%8,%9}, {%0,%1,%2,%3};"
        : "+f"(d[0]), "+f"(d[1]), "+f"(d[2]), "+f"(d[3])
        : "r"(a[0]), "r"(a[1]), "r"(a[2]), "r"(a[3]), "r"(b[0]), "r"(b[1]));
}

// ---------------- smem: 2 stages x (A_hi 8K | A_lo 8K | B_hi 8K | B_lo 8K) --
#define STAGE_BYTES 32768
#define SM_TOTAL    (2 * STAGE_BYTES)
// tiles: 128 rows x 32 bf16 (64B rows), swizzle: 16B-chunk ^= (row>>1)&3

__device__ __forceinline__ void ldg_chunk(const uint32_t* __restrict__ base, int ld,
                                          int row0, int kc, int tid, uint4* s) {
#pragma unroll
    for (int it = 0; it < 4; it++) {
        int slot = tid + it * 256;
        int row = slot >> 3, c8 = slot & 7;
        s[it] = *(const uint4*)(base + (size_t)(row0 + row) * ld + kc * 32 + c8 * 4);
    }
}

__device__ __forceinline__ void split_store_chunk(uint32_t hiB, uint32_t loB,
                                                  int tid, const uint4* s) {
#pragma unroll
    for (int it = 0; it < 4; it++) {
        int slot = tid + it * 256;
        int row = slot >> 3, c8 = slot & 7;
        uint32_t off = (uint32_t)row * 64
                     + ((((c8 >> 1) ^ ((row >> 1) & 3)) << 4) | ((c8 & 1) << 3));
        uint32_t h0 = __byte_perm(s[it].x, s[it].y, 0x5410);
        uint32_t h1 = __byte_perm(s[it].z, s[it].w, 0x5410);
        uint32_t l0 = __byte_perm(s[it].x, s[it].y, 0x7632);
        uint32_t l1 = __byte_perm(s[it].z, s[it].w, 0x7632);
        asm volatile("st.shared.v2.b32 [%0], {%1,%2};" :: "r"(hiB + off), "r"(h0), "r"(h1) : "memory");
        asm volatile("st.shared.v2.b32 [%0], {%1,%2};" :: "r"(loB + off), "r"(l0), "r"(l1) : "memory");
    }
}

// ---------------- bf16x3 mma.sync GEMM --------------------------------------
// D[m,n] = alpha * sum_k A[m,k]*B[n,k] (+bias); A,B packed hi/lo u32, K-major.
// BIAS_MODE: 0 none, 1 bias[n], 2 bias[m].  OUT_PACKED: 1 packed hi/lo, 0 fp32.
template<int BIAS_MODE, int OUT_PACKED>
__global__ void __launch_bounds__(256)
gemm_mma(const uint32_t* __restrict__ A, const uint32_t* __restrict__ B,
         const float* __restrict__ bias, void* __restrict__ Cv,
         int lda, int ldb, int ldc, int nK,
         size_t sA, size_t sB, size_t sC, float alpha)
{
    extern __shared__ __align__(1024) char smem[];
    const uint32_t sm = smem_u32(smem);
    const int tid  = threadIdx.x;
    const int lane = tid & 31;
    const int wid  = tid >> 5;
    const int m0   = blockIdx.y * 128;
    const int n0   = blockIdx.x * 128;
    const int mW   = (wid >> 2) * 64;
    const int nW   = (wid & 3) * 32;

    A += (size_t)blockIdx.z * sA;
    B += (size_t)blockIdx.z * sB;

    float acc[4][4][4];
#pragma unroll
    for (int i = 0; i < 4; i++)
#pragma unroll
        for (int j = 0; j < 4; j++) {
            acc[i][j][0] = 0.f; acc[i][j][1] = 0.f; acc[i][j][2] = 0.f; acc[i][j][3] = 0.f;
        }

    // lane-invariant fragment addressing (swizzle folded into chunk index)
    const uint32_t rl   = lane & 15;            // A: row within 16
    const uint32_t khA  = lane >> 4;            // A: k-half
    const uint32_t swA  = (rl >> 1) & 3;
    const uint32_t aRow = (uint32_t)(mW + rl) * 64;
    const uint32_t rnl  = ((lane >> 4) << 3) | (lane & 7);  // B: row within 16
    const uint32_t khB  = (lane >> 3) & 1;
    const uint32_t swB  = (rnl >> 1) & 3;
    const uint32_t bRow = (uint32_t)(nW + rnl) * 64;

    uint4 sa[4], sb[4];

    // prologue: chunk 0 -> stage 0
    ldg_chunk(A, lda, m0, 0, tid, sa);
    ldg_chunk(B, ldb, n0, 0, tid, sb);
    split_store_chunk(sm + 0,     sm + 8192,  tid, sa);
    split_store_chunk(sm + 16384, sm + 24576, tid, sb);
    __syncthreads();

    for (int i = 0; i < nK; i++) {
        const bool more = (i + 1) < nK;
        if (more) {
            ldg_chunk(A, lda, m0, i + 1, tid, sa);
            ldg_chunk(B, ldb, n0, i + 1, tid, sb);
        }
        const uint32_t stg = sm + (uint32_t)(i & 1) * STAGE_BYTES;

#pragma unroll
        for (int ks = 0; ks < 2; ks++) {
            const uint32_t aCh = (uint32_t)((ks * 2 + khA) ^ swA) << 4;
            const uint32_t bCh = (uint32_t)((ks * 2 + khB) ^ swB) << 4;
            uint32_t ah[4][4], al[4][4], bh[8], bl[8];
#pragma unroll
            for (int mt = 0; mt < 4; mt++) {
                LDSM_X4(ah[mt][0], ah[mt][1], ah[mt][2], ah[mt][3],
                        stg + aRow + mt * 1024 + aCh);
                LDSM_X4(al[mt][0], al[mt][1], al[mt][2], al[mt][3],
                        stg + 8192 + aRow + mt * 1024 + aCh);
            }
            LDSM_X4(bh[0], bh[1], bh[2], bh[3], stg + 16384 + bRow + bCh);
            LDSM_X4(bh[4], bh[5], bh[6], bh[7], stg + 16384 + bRow + 1024 + bCh);
            LDSM_X4(bl[0], bl[1], bl[2], bl[3], stg + 24576 + bRow + bCh);
            LDSM_X4(bl[4], bl[5], bl[6], bl[7], stg + 24576 + bRow + 1024 + bCh);

#pragma unroll
            for (int mt = 0; mt < 4; mt++)
#pragma unroll
                for (int nt = 0; nt < 4; nt++) {
                    mma16816(acc[mt][nt], ah[mt], &bh[nt * 2]);   // hi*hi
                    mma16816(acc[mt][nt], ah[mt], &bl[nt * 2]);   // hi*lo
                    mma16816(acc[mt][nt], al[mt], &bh[nt * 2]);   // lo*hi
                }
        }

        if (more) {
            const uint32_t nstg = sm + (uint32_t)((i + 1) & 1) * STAGE_BYTES;
            split_store_chunk(nstg + 0,     nstg + 8192,  tid, sa);
            split_store_chunk(nstg + 16384, nstg + 24576, tid, sb);
        }
        __syncthreads();
    }

    // ---- epilogue ----
    const int g  = lane >> 2;
    const int tg = lane & 3;
#pragma unroll
    for (int mt = 0; mt < 4; mt++) {
        const int m = m0 + mW + mt * 16 + g;
        float bm0 = 0.f, bm8 = 0.f;
        if (BIAS_MODE == 2) { bm0 = bias[m]; bm8 = bias[m + 8]; }
#pragma unroll
        for (int nt = 0; nt < 4; nt++) {
            const int n = n0 + nW + nt * 8 + tg * 2;
            float d0 = acc[mt][nt][0] * alpha;
            float d1 = acc[mt][nt][1] * alpha;
            float d2 = acc[mt][nt][2] * alpha;
            float d3 = acc[mt][nt][3] * alpha;
            if (BIAS_MODE == 1) {
                float2 bb = *(const float2*)(bias + n);
                d0 += bb.x; d1 += bb.y; d2 += bb.x; d3 += bb.y;
            } else if (BIAS_MODE == 2) {
                d0 += bm0; d1 += bm0; d2 += bm8; d3 += bm8;
            }
            if (OUT_PACKED) {
                uint32_t* C = (uint32_t*)Cv + (size_t)blockIdx.z * sC;
                uint2 o0 = { pack_hl(d0), pack_hl(d1) };
                uint2 o1 = { pack_hl(d2), pack_hl(d3) };
                *(uint2*)(C + (size_t)m * ldc + n)       = o0;
                *(uint2*)(C + (size_t)(m + 8) * ldc + n) = o1;
            } else {
                float* C = (float*)Cv + (size_t)blockIdx.z * sC;
                float2 o0 = { d0, d1 };
                float2 o1 = { d2, d3 };
                *(float2*)(C + (size_t)m * ldc + n)       = o0;
                *(float2*)(C + (size_t)(m + 8) * ldc + n) = o1;
            }
        }
    }
}

// ---------------- converters -------------------------------------------------
__global__ void __launch_bounds__(256)
xpose_pack(const float* __restrict__ x, uint32_t* __restrict__ xT)
{
    __shared__ float t[32][33];
    const int tx = threadIdx.x, ty = threadIdx.y;
    const int s0 = blockIdx.x * 32, c0 = blockIdx.y * 32;
    const size_t bi = (size_t)blockIdx.z * Cin * Sn;
    const size_t bo = (size_t)blockIdx.z * Sn * Cin;
#pragma unroll
    for (int j = ty; j < 32; j += 8)
        t[j][tx] = x[bi + (size_t)(c0 + j) * Sn + s0 + tx];
    __syncthreads();
#pragma unroll
    for (int j = ty; j < 32; j += 8)
        xT[bo + (size_t)(s0 + j) * Cin + c0 + tx] = pack_hl(t[tx][j]);
}

__global__ void __launch_bounds__(256)
pack_f32(const float* __restrict__ in, uint32_t* __restrict__ out, int n4)
{
    int i = blockIdx.x * 256 + threadIdx.x;
    if (i < n4) {
        float4 v = ((const float4*)in)[i];
        uint4 o;
        o.x = pack_hl(v.x); o.y = pack_hl(v.y); o.z = pack_hl(v.z); o.w = pack_hl(v.w);
        ((uint4*)out)[i] = o;
    }
}

// ---------------- softmax (fp32 in place -> packed hi/lo) -------------------
__global__ void __launch_bounds__(256)
softmax2048(float* __restrict__ sc)
{
    float4* pv = (float4*)(sc + (size_t)blockIdx.x * 2048);
    uint4*  po = (uint4*)pv;
    const int tid = threadIdx.x;

    float4 v0 = pv[tid];
    float4 v1 = pv[tid + 256];
    __shared__ float red[8];

    float m = fmaxf(fmaxf(fmaxf(v0.x, v0.y), fmaxf(v0.z, v0.w)),
                    fmaxf(fmaxf(v1.x, v1.y), fmaxf(v1.z, v1.w)));
#pragma unroll
    for (int o = 16; o; o >>= 1) m = fmaxf(m, __shfl_xor_sync(0xffffffffu, m, o));
    if ((tid & 31) == 0) red[tid >> 5] = m;
    __syncthreads();
    float rowmax = red[0];
#pragma unroll
    for (int i = 1; i < 8; i++) rowmax = fmaxf(rowmax, red[i]);
    __syncthreads();

    v0.x = __expf(v0.x - rowmax); v0.y = __expf(v0.y - rowmax);
    v0.z = __expf(v0.z - rowmax); v0.w = __expf(v0.w - rowmax);
    v1.x = __expf(v1.x - rowmax); v1.y = __expf(v1.y - rowmax);
    v1.z = __expf(v1.z - rowmax); v1.w = __expf(v1.w - rowmax);

    float s = (v0.x + v0.y + v0.z + v0.w) + (v1.x + v1.y + v1.z + v1.w);
#pragma unroll
    for (int o = 16; o; o >>= 1) s += __shfl_xor_sync(0xffffffffu, s, o);
    if ((tid & 31) == 0) red[tid >> 5] = s;
    __syncthreads();
    float tot = red[0];
#pragma unroll
    for (int i = 1; i < 8; i++) tot += red[i];
    const float inv = 1.0f / tot;

    uint4 o0, o1;
    o0.x = pack_hl(v0.x * inv); o0.y = pack_hl(v0.y * inv);
    o0.z = pack_hl(v0.z * inv); o0.w = pack_hl(v0.w * inv);
    o1.x = pack_hl(v1.x * inv); o1.y = pack_hl(v1.y * inv);
    o1.z = pack_hl(v1.z * inv); o1.w = pack_hl(v1.w * inv);
    po[tid]       = o0;
    po[tid + 256] = o1;
}

// -----------------------------------------------------------------------------
extern "C" void kernel_launch(void* const* d_in, const int* in_sizes, int n_in,
                              void* d_out, int out_size)
{
    (void)in_sizes; (void)n_in; (void)out_size;
    const float* x  = (const float*)d_in[0];
    const float* wq = (const float*)d_in[1];
    const float* bq = (const float*)d_in[2];
    const float* wk = (const float*)d_in[3];
    const float* bk = (const float*)d_in[4];
    const float* wv = (const float*)d_in[5];
    const float* bv = (const float*)d_in[6];
    float* out = (float*)d_out;

    uint32_t *xT, *wqp, *wkp, *wvp, *qp, *kp, *vp;
    float* sc;
    cudaGetSymbolAddress((void**)&xT,  g_xT);
    cudaGetSymbolAddress((void**)&wqp, g_wq);
    cudaGetSymbolAddress((void**)&wkp, g_wk);
    cudaGetSymbolAddress((void**)&wvp, g_wv);
    cudaGetSymbolAddress((void**)&qp,  g_qp);
    cudaGetSymbolAddress((void**)&kp,  g_kp);
    cudaGetSymbolAddress((void**)&vp,  g_vp);
    cudaGetSymbolAddress((void**)&sc,  g_sc);

    cudaFuncSetAttribute(gemm_mma<1, 1>, cudaFuncAttributeMaxDynamicSharedMemorySize, SM_TOTAL);
    cudaFuncSetAttribute(gemm_mma<2, 1>, cudaFuncAttributeMaxDynamicSharedMemorySize, SM_TOTAL);
    cudaFuncSetAttribute(gemm_mma<0, 0>, cudaFuncAttributeMaxDynamicSharedMemorySize, SM_TOTAL);

    // convert inputs
    xpose_pack<<<dim3(Sn / 32, Cin / 32, Bn), dim3(32, 8)>>>(x, xT);
    pack_f32<<<(KD * Cin / 4 + 255) / 256, 256>>>(wq, wqp, KD * Cin / 4);
    pack_f32<<<(KD * Cin / 4 + 255) / 256, 256>>>(wk, wkp, KD * Cin / 4);
    pack_f32<<<(OD * Cin / 4 + 255) / 256, 256>>>(wv, wvp, OD * Cin / 4);

    const size_t sxT = (size_t)Sn * Cin;
    const size_t sq  = (size_t)Sn * KD;
    const size_t sv  = (size_t)OD * Sn;
    const size_t ssc = (size_t)Sn * Sn;

    // q = xT @ Wq^T + bq -> (B,S,KD) packed   [m=s, n=kd, k=c]
    gemm_mma<1, 1><<<dim3(KD / 128, Sn / 128, Bn), 256, SM_TOTAL>>>(
        xT, wqp, bq, qp, Cin, Cin, KD, Cin / 32, sxT, 0, sq, 1.0f);
    // k = xT @ Wk^T + bk -> (B,S,KD) packed
    gemm_mma<1, 1><<<dim3(KD / 128, Sn / 128, Bn), 256, SM_TOTAL>>>(
        xT, wkp, bk, kp, Cin, Cin, KD, Cin / 32, sxT, 0, sq, 1.0f);
    // v = Wv @ x + bv -> (B,OD,S) packed      [m=o, n=s, k=c]
    gemm_mma<2, 1><<<dim3(Sn / 128, OD / 128, Bn), 256, SM_TOTAL>>>(
        wvp, xT, bv, vp, Cin, Cin, Sn, Cin / 32, 0, sxT, sv, 1.0f);

    // scores = q @ k^T / sqrt(KD) -> (B,S,S) fp32   [m=s, n=t, k=kd]
    gemm_mma<0, 0><<<dim3(Sn / 128, Sn / 128, Bn), 256, SM_TOTAL>>>(
        qp, kp, nullptr, sc, KD, KD, Sn, KD / 32, sq, sq, ssc, 0.04419417382415922f);

    // softmax rows, in-place repack to hi/lo
    softmax2048<<<Bn * Sn, 256>>>(sc);

    // out = v @ attn^T -> (B,OD,S) fp32 into d_out  [m=o, n=s, k=t]
    gemm_mma<0, 0><<<dim3(Sn / 128, OD / 128, Bn), 256, SM_TOTAL>>>(
        vp, (const uint32_t*)sc, nullptr, out, Sn, Sn, Sn, Sn / 32, sv, ssc, sv, 1.0f);
}

// round 4
// speedup vs baseline: 3.0667x; 1.0416x over previous
#include <cuda_runtime.h>
#include <cuda_bf16.h>
#include <cstdint>
#include <math.h>

#define Bn  8
#define Cin 1024
#define Sn  2048
#define KD  512
#define OD  1024

typedef __nv_bfloat16 bf16;

// ---------------- scratch: separate hi / lo planes --------------------------
__device__ __align__(128) bf16 g_xT_h[(size_t)Bn * Sn * Cin];
__device__ __align__(128) bf16 g_xT_l[(size_t)Bn * Sn * Cin];
__device__ __align__(128) bf16 g_wq_h[(size_t)KD * Cin];
__device__ __align__(128) bf16 g_wq_l[(size_t)KD * Cin];
__device__ __align__(128) bf16 g_wk_h[(size_t)KD * Cin];
__device__ __align__(128) bf16 g_wk_l[(size_t)KD * Cin];
__device__ __align__(128) bf16 g_wv_h[(size_t)OD * Cin];
__device__ __align__(128) bf16 g_wv_l[(size_t)OD * Cin];
__device__ __align__(128) bf16 g_q_h[(size_t)Bn * Sn * KD];
__device__ __align__(128) bf16 g_q_l[(size_t)Bn * Sn * KD];
__device__ __align__(128) bf16 g_k_h[(size_t)Bn * Sn * KD];
__device__ __align__(128) bf16 g_k_l[(size_t)Bn * Sn * KD];
__device__ __align__(128) bf16 g_v_h[(size_t)Bn * OD * Sn];
__device__ __align__(128) bf16 g_v_l[(size_t)Bn * OD * Sn];
__device__ __align__(128) bf16 g_a_h[(size_t)Bn * Sn * Sn];
__device__ __align__(128) bf16 g_a_l[(size_t)Bn * Sn * Sn];
__device__ __align__(128) float g_sc[(size_t)Bn * Sn * Sn];

// ---------------- helpers ----------------------------------------------------
__device__ __forceinline__ uint32_t smem_u32(const void* p) {
    uint32_t a;
    asm("{ .reg .u64 t; cvta.to.shared.u64 t, %1; cvt.u32.u64 %0, t; }" : "=r"(a) : "l"(p));
    return a;
}

__device__ __forceinline__ void split_hl(float v, bf16& h, bf16& l) {
    h = __float2bfloat16(v);
    l = __float2bfloat16(v - __bfloat162float(h));
}

#define LDSM_X4(r0, r1, r2, r3, addr) \
    asm volatile("ldmatrix.sync.aligned.m8n8.x4.shared.b16 {%0,%1,%2,%3}, [%4];" \
                 : "=r"(r0), "=r"(r1), "=r"(r2), "=r"(r3) : "r"(addr))

__device__ __forceinline__ void mma16816(float* d, const uint32_t* a, const uint32_t* b) {
    asm volatile(
        "mma.sync.aligned.m16n8k16.row.col.f32.bf16.bf16.f32 "
        "{%0,%1,%2,%3}, {%4,%5,%6,%7}, {%8,%9}, {%0,%1,%2,%3};"
        : "+f"(d[0]), "+f"(d[1]), "+f"(d[2]), "+f"(d[3])
        : "r"(a[0]), "r"(a[1]), "r"(a[2]), "r"(a[3]), "r"(b[0]), "r"(b[1]));
}

#define CP_ASYNC16(dst, src) \
    asm volatile("cp.async.cg.shared.global [%0], [%1], 16;" :: "r"(dst), "l"(src) : "memory")
#define CP_COMMIT()  asm volatile("cp.async.commit_group;" ::: "memory")
#define CP_WAIT(n)   asm volatile("cp.async.wait_group %0;" :: "n"(n) : "memory")

// ---------------- smem: 3 stages x (Ah 8K | Al 8K | Bh 8K | Bl 8K) ----------
#define STAGE_BYTES 32768
#define NSTAGE      3
#define SM_TOTAL    (NSTAGE * STAGE_BYTES)
// tile: 128 rows x 32 bf16 (64B rows); 16B-chunk swizzle: c4 ^= (row>>1)&3

__device__ __forceinline__ void cp_tile(uint32_t sdst, const bf16* __restrict__ g,
                                        int ld, int row0, int kc, int tid) {
#pragma unroll
    for (int it = 0; it < 2; it++) {
        int slot = tid + it * 256;                 // 0..511
        int row  = slot >> 2;
        int c4   = slot & 3;
        uint32_t off = (uint32_t)row * 64 + (uint32_t)((c4 ^ ((row >> 1) & 3)) << 4);
        CP_ASYNC16(sdst + off, g + (size_t)(row0 + row) * ld + kc * 32 + c4 * 8);
    }
}

// ---------------- bf16x3 mma.sync GEMM with cp.async pipeline ---------------
// D[m,n] = alpha * sum_k A[m,k]*B[n,k] (+bias); A,B hi/lo bf16 planes, K-major.
// BIAS_MODE: 0 none, 1 bias[n], 2 bias[m].  OUT_HL: 1 -> hi/lo planes, 0 -> fp32.
template<int BIAS_MODE, int OUT_HL>
__global__ void __launch_bounds__(256)
gemm_mma(const bf16* __restrict__ Ah, const bf16* __restrict__ Al,
         const bf16* __restrict__ Bh, const bf16* __restrict__ Bl,
         const float* __restrict__ bias,
         void* __restrict__ Ch, void* __restrict__ Cl,
         int lda, int ldb, int ldc, int nK,
         size_t sA, size_t sB, size_t sC, float alpha)
{
    extern __shared__ __align__(1024) char smem[];
    const uint32_t sm = smem_u32(smem);
    const int tid  = threadIdx.x;
    const int lane = tid & 31;
    const int wid  = tid >> 5;
    const int m0   = blockIdx.y * 128;
    const int n0   = blockIdx.x * 128;
    const int mW   = (wid >> 2) * 64;
    const int nW   = (wid & 3) * 32;

    Ah += (size_t)blockIdx.z * sA;  Al += (size_t)blockIdx.z * sA;
    Bh += (size_t)blockIdx.z * sB;  Bl += (size_t)blockIdx.z * sB;

    float acc[4][4][4];
#pragma unroll
    for (int i = 0; i < 4; i++)
#pragma unroll
        for (int j = 0; j < 4; j++) {
            acc[i][j][0] = 0.f; acc[i][j][1] = 0.f; acc[i][j][2] = 0.f; acc[i][j][3] = 0.f;
        }

    // fragment addressing (swizzle folded into chunk index)
    const uint32_t rl   = lane & 15;
    const uint32_t khA  = lane >> 4;
    const uint32_t swA  = (rl >> 1) & 3;
    const uint32_t aRow = (uint32_t)(mW + rl) * 64;
    const uint32_t rnl  = ((lane >> 4) << 3) | (lane & 7);
    const uint32_t khB  = (lane >> 3) & 1;
    const uint32_t swB  = (rnl >> 1) & 3;
    const uint32_t bRow = (uint32_t)(nW + rnl) * 64;

    // prologue: stages 0 and 1
#pragma unroll
    for (int p = 0; p < 2; p++) {
        if (p < nK) {
            const uint32_t st = sm + p * STAGE_BYTES;
            cp_tile(st,         Ah, lda, m0, p, tid);
            cp_tile(st + 8192,  Al, lda, m0, p, tid);
            cp_tile(st + 16384, Bh, ldb, n0, p, tid);
            cp_tile(st + 24576, Bl, ldb, n0, p, tid);
        }
        CP_COMMIT();
    }

    for (int i = 0; i < nK; i++) {
        CP_WAIT(1);
        __syncthreads();

        // issue chunk i+2 into stage (i+2)%3
        {
            const int nx = i + 2;
            if (nx < nK) {
                const uint32_t st = sm + (uint32_t)(nx % NSTAGE) * STAGE_BYTES;
                cp_tile(st,         Ah, lda, m0, nx, tid);
                cp_tile(st + 8192,  Al, lda, m0, nx, tid);
                cp_tile(st + 16384, Bh, ldb, n0, nx, tid);
                cp_tile(st + 24576, Bl, ldb, n0, nx, tid);
            }
            CP_COMMIT();
        }

        const uint32_t stg = sm + (uint32_t)(i % NSTAGE) * STAGE_BYTES;
#pragma unroll
        for (int ks = 0; ks < 2; ks++) {
            const uint32_t aCh = (uint32_t)((ks * 2 + khA) ^ swA) << 4;
            const uint32_t bCh = (uint32_t)((ks * 2 + khB) ^ swB) << 4;
            uint32_t ah[4][4], al[4][4], bh[8], bl[8];
#pragma unroll
            for (int mt = 0; mt < 4; mt++) {
                LDSM_X4(ah[mt][0], ah[mt][1], ah[mt][2], ah[mt][3],
                        stg + aRow + mt * 1024 + aCh);
                LDSM_X4(al[mt][0], al[mt][1], al[mt][2], al[mt][3],
                        stg + 8192 + aRow + mt * 1024 + aCh);
            }
            LDSM_X4(bh[0], bh[1], bh[2], bh[3], stg + 16384 + bRow + bCh);
            LDSM_X4(bh[4], bh[5], bh[6], bh[7], stg + 16384 + bRow + 1024 + bCh);
            LDSM_X4(bl[0], bl[1], bl[2], bl[3], stg + 24576 + bRow + bCh);
            LDSM_X4(bl[4], bl[5], bl[6], bl[7], stg + 24576 + bRow + 1024 + bCh);

#pragma unroll
            for (int mt = 0; mt < 4; mt++)
#pragma unroll
                for (int nt = 0; nt < 4; nt++) {
                    mma16816(acc[mt][nt], ah[mt], &bh[nt * 2]);
                    mma16816(acc[mt][nt], ah[mt], &bl[nt * 2]);
                    mma16816(acc[mt][nt], al[mt], &bh[nt * 2]);
                }
        }
        __syncthreads();
    }

    // ---- epilogue ----
    const int g  = lane >> 2;
    const int tg = lane & 3;
#pragma unroll
    for (int mt = 0; mt < 4; mt++) {
        const int m = m0 + mW + mt * 16 + g;
        float bm0 = 0.f, bm8 = 0.f;
        if (BIAS_MODE == 2) { bm0 = bias[m]; bm8 = bias[m + 8]; }
#pragma unroll
        for (int nt = 0; nt < 4; nt++) {
            const int n = n0 + nW + nt * 8 + tg * 2;
            float d0 = acc[mt][nt][0] * alpha;
            float d1 = acc[mt][nt][1] * alpha;
            float d2 = acc[mt][nt][2] * alpha;
            float d3 = acc[mt][nt][3] * alpha;
            if (BIAS_MODE == 1) {
                float2 bb = *(const float2*)(bias + n);
                d0 += bb.x; d1 += bb.y; d2 += bb.x; d3 += bb.y;
            } else if (BIAS_MODE == 2) {
                d0 += bm0; d1 += bm0; d2 += bm8; d3 += bm8;
            }
            if (OUT_HL) {
                bf16 h0, l0, h1, l1, h2, l2, h3, l3;
                split_hl(d0, h0, l0); split_hl(d1, h1, l1);
                split_hl(d2, h2, l2); split_hl(d3, h3, l3);
                bf16* CH = (bf16*)Ch + (size_t)blockIdx.z * sC;
                bf16* CL = (bf16*)Cl + (size_t)blockIdx.z * sC;
                *(__nv_bfloat162*)(CH + (size_t)m * ldc + n)       = __nv_bfloat162(h0, h1);
                *(__nv_bfloat162*)(CH + (size_t)(m + 8) * ldc + n) = __nv_bfloat162(h2, h3);
                *(__nv_bfloat162*)(CL + (size_t)m * ldc + n)       = __nv_bfloat162(l0, l1);
                *(__nv_bfloat162*)(CL + (size_t)(m + 8) * ldc + n) = __nv_bfloat162(l2, l3);
            } else {
                float* C = (float*)Ch + (size_t)blockIdx.z * sC;
                float2 o0 = { d0, d1 };
                float2 o1 = { d2, d3 };
                *(float2*)(C + (size_t)m * ldc + n)       = o0;
                *(float2*)(C + (size_t)(m + 8) * ldc + n) = o1;
            }
        }
    }
}

// ---------------- converters --------------------------------------------------
__global__ void __launch_bounds__(256)
xpose_pack(const float* __restrict__ x, bf16* __restrict__ xh, bf16* __restrict__ xl)
{
    __shared__ float t[32][33];
    const int tx = threadIdx.x, ty = threadIdx.y;
    const int s0 = blockIdx.x * 32, c0 = blockIdx.y * 32;
    const size_t bi = (size_t)blockIdx.z * Cin * Sn;
    const size_t bo = (size_t)blockIdx.z * Sn * Cin;
#pragma unroll
    for (int j = ty; j < 32; j += 8)
        t[j][tx] = x[bi + (size_t)(c0 + j) * Sn + s0 + tx];
    __syncthreads();
#pragma unroll
    for (int j = ty; j < 32; j += 8) {
        bf16 h, l;
        split_hl(t[tx][j], h, l);
        xh[bo + (size_t)(s0 + j) * Cin + c0 + tx] = h;
        xl[bo + (size_t)(s0 + j) * Cin + c0 + tx] = l;
    }
}

__global__ void __launch_bounds__(256)
pack_f32(const float* __restrict__ in, bf16* __restrict__ oh, bf16* __restrict__ ol, int n4)
{
    int i = blockIdx.x * 256 + threadIdx.x;
    if (i < n4) {
        float4 v = ((const float4*)in)[i];
        bf16 h0, l0, h1, l1, h2, l2, h3, l3;
        split_hl(v.x, h0, l0); split_hl(v.y, h1, l1);
        split_hl(v.z, h2, l2); split_hl(v.w, h3, l3);
        uint2 ho, lo;
        ho.x = (uint32_t)__bfloat16_as_ushort(h0) | ((uint32_t)__bfloat16_as_ushort(h1) << 16);
        ho.y = (uint32_t)__bfloat16_as_ushort(h2) | ((uint32_t)__bfloat16_as_ushort(h3) << 16);
        lo.x = (uint32_t)__bfloat16_as_ushort(l0) | ((uint32_t)__bfloat16_as_ushort(l1) << 16);
        lo.y = (uint32_t)__bfloat16_as_ushort(l2) | ((uint32_t)__bfloat16_as_ushort(l3) << 16);
        ((uint2*)oh)[i] = ho;
        ((uint2*)ol)[i] = lo;
    }
}

// ---------------- softmax: fp32 scores -> hi/lo bf16 planes -----------------
__global__ void __launch_bounds__(256)
softmax2048(const float* __restrict__ sc, bf16* __restrict__ ah, bf16* __restrict__ al)
{
    const float4* pv = (const float4*)(sc + (size_t)blockIdx.x * 2048);
    const int tid = threadIdx.x;

    float4 v0 = pv[tid];
    float4 v1 = pv[tid + 256];
    __shared__ float red[8];

    float m = fmaxf(fmaxf(fmaxf(v0.x, v0.y), fmaxf(v0.z, v0.w)),
                    fmaxf(fmaxf(v1.x, v1.y), fmaxf(v1.z, v1.w)));
#pragma unroll
    for (int o = 16; o; o >>= 1) m = fmaxf(m, __shfl_xor_sync(0xffffffffu, m, o));
    if ((tid & 31) == 0) red[tid >> 5] = m;
    __syncthreads();
    float rowmax = red[0];
#pragma unroll
    for (int i = 1; i < 8; i++) rowmax = fmaxf(rowmax, red[i]);
    __syncthreads();

    v0.x = __expf(v0.x - rowmax); v0.y = __expf(v0.y - rowmax);
    v0.z = __expf(v0.z - rowmax); v0.w = __expf(v0.w - rowmax);
    v1.x = __expf(v1.x - rowmax); v1.y = __expf(v1.y - rowmax);
    v1.z = __expf(v1.z - rowmax); v1.w = __expf(v1.w - rowmax);

    float s = (v0.x + v0.y + v0.z + v0.w) + (v1.x + v1.y + v1.z + v1.w);
#pragma unroll
    for (int o = 16; o; o >>= 1) s += __shfl_xor_sync(0xffffffffu, s, o);
    if ((tid & 31) == 0) red[tid >> 5] = s;
    __syncthreads();
    float tot = red[0];
#pragma unroll
    for (int i = 1; i < 8; i++) tot += red[i];
    const float inv = 1.0f / tot;

    const size_t row = (size_t)blockIdx.x * 2048;
    float vals[8] = { v0.x * inv, v0.y * inv, v0.z * inv, v0.w * inv,
                      v1.x * inv, v1.y * inv, v1.z * inv, v1.w * inv };
    bf16 h[8], l[8];
#pragma unroll
    for (int i = 0; i < 8; i++) split_hl(vals[i], h[i], l[i]);

    uint2 ho0, lo0, ho1, lo1;
    ho0.x = (uint32_t)__bfloat16_as_ushort(h[0]) | ((uint32_t)__bfloat16_as_ushort(h[1]) << 16);
    ho0.y = (uint32_t)__bfloat16_as_ushort(h[2]) | ((uint32_t)__bfloat16_as_ushort(h[3]) << 16);
    lo0.x = (uint32_t)__bfloat16_as_ushort(l[0]) | ((uint32_t)__bfloat16_as_ushort(l[1]) << 16);
    lo0.y = (uint32_t)__bfloat16_as_ushort(l[2]) | ((uint32_t)__bfloat16_as_ushort(l[3]) << 16);
    ho1.x = (uint32_t)__bfloat16_as_ushort(h[4]) | ((uint32_t)__bfloat16_as_ushort(h[5]) << 16);
    ho1.y = (uint32_t)__bfloat16_as_ushort(h[6]) | ((uint32_t)__bfloat16_as_ushort(h[7]) << 16);
    lo1.x = (uint32_t)__bfloat16_as_ushort(l[4]) | ((uint32_t)__bfloat16_as_ushort(l[5]) << 16);
    lo1.y = (uint32_t)__bfloat16_as_ushort(l[6]) | ((uint32_t)__bfloat16_as_ushort(l[7]) << 16);

    *(uint2*)(ah + row + tid * 4)        = ho0;
    *(uint2*)(al + row + tid * 4)        = lo0;
    *(uint2*)(ah + row + 1024 + tid * 4) = ho1;
    *(uint2*)(al + row + 1024 + tid * 4) = lo1;
}

// -----------------------------------------------------------------------------
extern "C" void kernel_launch(void* const* d_in, const int* in_sizes, int n_in,
                              void* d_out, int out_size)
{
    (void)in_sizes; (void)n_in; (void)out_size;
    const float* x  = (const float*)d_in[0];
    const float* wq = (const float*)d_in[1];
    const float* bq = (const float*)d_in[2];
    const float* wk = (const float*)d_in[3];
    const float* bk = (const float*)d_in[4];
    const float* wv = (const float*)d_in[5];
    const float* bv = (const float*)d_in[6];
    float* out = (float*)d_out;

    bf16 *xh, *xl, *wqh, *wql, *wkh, *wkl, *wvh, *wvl;
    bf16 *qh, *ql, *kh, *kl, *vh, *vl, *ah, *al;
    float* sc;
    cudaGetSymbolAddress((void**)&xh,  g_xT_h);  cudaGetSymbolAddress((void**)&xl,  g_xT_l);
    cudaGetSymbolAddress((void**)&wqh, g_wq_h);  cudaGetSymbolAddress((void**)&wql, g_wq_l);
    cudaGetSymbolAddress((void**)&wkh, g_wk_h);  cudaGetSymbolAddress((void**)&wkl, g_wk_l);
    cudaGetSymbolAddress((void**)&wvh, g_wv_h);  cudaGetSymbolAddress((void**)&wvl, g_wv_l);
    cudaGetSymbolAddress((void**)&qh,  g_q_h);   cudaGetSymbolAddress((void**)&ql,  g_q_l);
    cudaGetSymbolAddress((void**)&kh,  g_k_h);   cudaGetSymbolAddress((void**)&kl,  g_k_l);
    cudaGetSymbolAddress((void**)&vh,  g_v_h);   cudaGetSymbolAddress((void**)&vl,  g_v_l);
    cudaGetSymbolAddress((void**)&ah,  g_a_h);   cudaGetSymbolAddress((void**)&al,  g_a_l);
    cudaGetSymbolAddress((void**)&sc,  g_sc);

    cudaFuncSetAttribute(gemm_mma<1, 1>, cudaFuncAttributeMaxDynamicSharedMemorySize, SM_TOTAL);
    cudaFuncSetAttribute(gemm_mma<2, 1>, cudaFuncAttributeMaxDynamicSharedMemorySize, SM_TOTAL);
    cudaFuncSetAttribute(gemm_mma<0, 0>, cudaFuncAttributeMaxDynamicSharedMemorySize, SM_TOTAL);

    // convert inputs
    xpose_pack<<<dim3(Sn / 32, Cin / 32, Bn), dim3(32, 8)>>>(x, xh, xl);
    pack_f32<<<(KD * Cin / 4 + 255) / 256, 256>>>(wq, wqh, wql, KD * Cin / 4);
    pack_f32<<<(KD * Cin / 4 + 255) / 256, 256>>>(wk, wkh, wkl, KD * Cin / 4);
    pack_f32<<<(OD * Cin / 4 + 255) / 256, 256>>>(wv, wvh, wvl, OD * Cin / 4);

    const size_t sxT = (size_t)Sn * Cin;
    const size_t sq  = (size_t)Sn * KD;
    const size_t sv  = (size_t)OD * Sn;
    const size_t ssc = (size_t)Sn * Sn;

    // q = xT @ Wq^T + bq -> (B,S,KD)   [m=s, n=kd, k=c]
    gemm_mma<1, 1><<<dim3(KD / 128, Sn / 128, Bn), 256, SM_TOTAL>>>(
        xh, xl, wqh, wql, bq, qh, ql, Cin, Cin, KD, Cin / 32, sxT, 0, sq, 1.0f);
    // k = xT @ Wk^T + bk -> (B,S,KD)
    gemm_mma<1, 1><<<dim3(KD / 128, Sn / 128, Bn), 256, SM_TOTAL>>>(
        xh, xl, wkh, wkl, bk, kh, kl, Cin, Cin, KD, Cin / 32, sxT, 0, sq, 1.0f);
    // v = Wv @ x + bv -> (B,OD,S)       [m=o, n=s, k=c]
    gemm_mma<2, 1><<<dim3(Sn / 128, OD / 128, Bn), 256, SM_TOTAL>>>(
        wvh, wvl, xh, xl, bv, vh, vl, Cin, Cin, Sn, Cin / 32, 0, sxT, sv, 1.0f);

    // scores = q @ k^T / sqrt(KD) -> fp32 (B,S,S)   [m=s, n=t, k=kd]
    gemm_mma<0, 0><<<dim3(Sn / 128, Sn / 128, Bn), 256, SM_TOTAL>>>(
        qh, ql, kh, kl, nullptr, sc, nullptr, KD, KD, Sn, KD / 32, sq, sq, ssc,
        0.04419417382415922f);

    // softmax rows -> attn hi/lo planes
    softmax2048<<<Bn * Sn, 256>>>(sc, ah, al);

    // out = v @ attn^T -> (B,OD,S) fp32 into d_out  [m=o, n=s, k=t]
    gemm_mma<0, 0><<<dim3(Sn / 128, OD / 128, Bn), 256, SM_TOTAL>>>(
        vh, vl, ah, al, nullptr, out, nullptr, Sn, Sn, Sn, Sn / 32, sv, ssc, sv, 1.0f);
}

// round 5
// speedup vs baseline: 3.3878x; 1.1047x over previous
#include <cuda_runtime.h>
#include <cuda_bf16.h>
#include <cstdint>
#include <math.h>

#define Bn  8
#define Cin 1024
#define Sn  2048
#define KD  512
#define OD  1024
#define QKN 1024   // merged q|k output width

typedef __nv_bfloat16 bf16;

// ---------------- scratch: separate hi / lo planes --------------------------
__device__ __align__(128) bf16 g_xT_h[(size_t)Bn * Sn * Cin];
__device__ __align__(128) bf16 g_xT_l[(size_t)Bn * Sn * Cin];
__device__ __align__(128) bf16 g_wqk_h[(size_t)QKN * Cin];
__device__ __align__(128) bf16 g_wqk_l[(size_t)QKN * Cin];
__device__ __align__(128) bf16 g_wv_h[(size_t)OD * Cin];
__device__ __align__(128) bf16 g_wv_l[(size_t)OD * Cin];
__device__ __align__(128) float g_bqk[QKN];
__device__ __align__(128) bf16 g_qk_h[(size_t)Bn * Sn * QKN];  // q cols 0-511, k cols 512-1023
__device__ __align__(128) bf16 g_qk_l[(size_t)Bn * Sn * QKN];
__device__ __align__(128) bf16 g_v_h[(size_t)Bn * OD * Sn];
__device__ __align__(128) bf16 g_v_l[(size_t)Bn * OD * Sn];
__device__ __align__(128) bf16 g_e_h[(size_t)Bn * Sn * Sn];    // unnormalized exp(scores)
__device__ __align__(128) bf16 g_e_l[(size_t)Bn * Sn * Sn];
__device__ __align__(128) float g_psum[(size_t)Bn * 16 * Sn];  // partial row sums per n-tile
__device__ __align__(128) float g_inv[(size_t)Bn * Sn];        // 1/rowsum

// ---------------- helpers ----------------------------------------------------
__device__ __forceinline__ uint32_t smem_u32(const void* p) {
    uint32_t a;
    asm("{ .reg .u64 t; cvta.to.shared.u64 t, %1; cvt.u32.u64 %0, t; }" : "=r"(a) : "l"(p));
    return a;
}

__device__ __forceinline__ void split_hl(float v, bf16& h, bf16& l) {
    h = __float2bfloat16(v);
    l = __float2bfloat16(v - __bfloat162float(h));
}

#define LDSM_X4(r0, r1, r2, r3, addr) \
    asm volatile("ldmatrix.sync.aligned.m8n8.x4.shared.b16 {%0,%1,%2,%3}, [%4];" \
                 : "=r"(r0), "=r"(r1), "=r"(r2), "=r"(r3) : "r"(addr))

__device__ __forceinline__ void mma16816(float* d, const uint32_t* a, const uint32_t* b) {
    asm volatile(
        "mma.sync.aligned.m16n8k16.row.col.f32.bf16.bf16.f32 "
        "{%0,%1,%2,%3}, {%4,%5,%6,%7}, {%8,%9}, {%0,%1,%2,%3};"
        : "+f"(d[0]), "+f"(d[1]), "+f"(d[2]), "+f"(d[3])
        : "r"(a[0]), "r"(a[1]), "r"(a[2]), "r"(a[3]), "r"(b[0]), "r"(b[1]));
}

#define CP_ASYNC16(dst, src) \
    asm volatile("cp.async.cg.shared.global [%0], [%1], 16;" :: "r"(dst), "l"(src) : "memory")
#define CP_COMMIT()  asm volatile("cp.async.commit_group;" ::: "memory")
#define CP_WAIT(n)   asm volatile("cp.async.wait_group %0;" :: "n"(n) : "memory")

// ---------------- smem: 3 stages x (Ah 8K | Al 8K | Bh 8K | Bl 8K) ----------
#define STAGE_BYTES 32768
#define NSTAGE      3
#define SM_TOTAL    (NSTAGE * STAGE_BYTES)
// tile: 128 rows x 32 bf16 (64B rows); 16B-chunk swizzle: c4 ^= (row>>1)&3

__device__ __forceinline__ void cp_tile(uint32_t sdst, const bf16* __restrict__ g,
                                        int ld, int row0, int kc, int tid) {
#pragma unroll
    for (int it = 0; it < 2; it++) {
        int slot = tid + it * 256;
        int row  = slot >> 2;
        int c4   = slot & 3;
        uint32_t off = (uint32_t)row * 64 + (uint32_t)((c4 ^ ((row >> 1) & 3)) << 4);
        CP_ASYNC16(sdst + off, g + (size_t)(row0 + row) * ld + kc * 32 + c4 * 8);
    }
}

// ---------------- bf16x3 mma.sync GEMM with cp.async pipeline ---------------
// D[m,n] = alpha * sum_k A[m,k]*B[n,k]; A,B hi/lo bf16 planes, K-major.
// EPI: 1 = +bias[n], HL-plane out           (qk projection)
//      2 = +bias[m], HL-plane out           (v projection)
//      3 = exp(d), HL-plane out + psum      (scores -> unnormalized softmax)
//      4 = d * aux[b*Sn + n], fp32 out      (PV with deferred normalization)
template<int EPI>
__global__ void __launch_bounds__(256)
gemm_mma(const bf16* __restrict__ Ah, const bf16* __restrict__ Al,
         const bf16* __restrict__ Bh, const bf16* __restrict__ Bl,
         const float* __restrict__ bias, float* __restrict__ aux,
         void* __restrict__ Ch, void* __restrict__ Cl,
         int lda, int ldb, int ldc, int nK,
         size_t sA, size_t sB, size_t sC, float alpha)
{
    extern __shared__ __align__(1024) char smem[];
    const uint32_t sm = smem_u32(smem);
    const int tid  = threadIdx.x;
    const int lane = tid & 31;
    const int wid  = tid >> 5;
    const int m0   = blockIdx.y * 128;
    const int n0   = blockIdx.x * 128;
    const int mW   = (wid >> 2) * 64;
    const int nW   = (wid & 3) * 32;

    Ah += (size_t)blockIdx.z * sA;  Al += (size_t)blockIdx.z * sA;
    Bh += (size_t)blockIdx.z * sB;  Bl += (size_t)blockIdx.z * sB;

    float acc[4][4][4];
#pragma unroll
    for (int i = 0; i < 4; i++)
#pragma unroll
        for (int j = 0; j < 4; j++) {
            acc[i][j][0] = 0.f; acc[i][j][1] = 0.f; acc[i][j][2] = 0.f; acc[i][j][3] = 0.f;
        }

    const uint32_t rl   = lane & 15;
    const uint32_t khA  = lane >> 4;
    const uint32_t swA  = (rl >> 1) & 3;
    const uint32_t aRow = (uint32_t)(mW + rl) * 64;
    const uint32_t rnl  = ((lane >> 4) << 3) | (lane & 7);
    const uint32_t khB  = (lane >> 3) & 1;
    const uint32_t swB  = (rnl >> 1) & 3;
    const uint32_t bRow = (uint32_t)(nW + rnl) * 64;

    // prologue: stages 0, 1
#pragma unroll
    for (int p = 0; p < 2; p++) {
        const uint32_t st = sm + p * STAGE_BYTES;
        cp_tile(st,         Ah, lda, m0, p, tid);
        cp_tile(st + 8192,  Al, lda, m0, p, tid);
        cp_tile(st + 16384, Bh, ldb, n0, p, tid);
        cp_tile(st + 24576, Bl, ldb, n0, p, tid);
        CP_COMMIT();
    }

    for (int i = 0; i < nK; i++) {
        CP_WAIT(1);
        __syncthreads();

        const uint32_t stg = sm + (uint32_t)(i % NSTAGE) * STAGE_BYTES;
#pragma unroll
        for (int ks = 0; ks < 2; ks++) {
            const uint32_t aCh = (uint32_t)((ks * 2 + khA) ^ swA) << 4;
            const uint32_t bCh = (uint32_t)((ks * 2 + khB) ^ swB) << 4;
            uint32_t ah[4][4], al[4][4], bh[8], bl[8];
#pragma unroll
            for (int mt = 0; mt < 4; mt++) {
                LDSM_X4(ah[mt][0], ah[mt][1], ah[mt][2], ah[mt][3],
                        stg + aRow + mt * 1024 + aCh);
                LDSM_X4(al[mt][0], al[mt][1], al[mt][2], al[mt][3],
                        stg + 8192 + aRow + mt * 1024 + aCh);
            }
            LDSM_X4(bh[0], bh[1], bh[2], bh[3], stg + 16384 + bRow + bCh);
            LDSM_X4(bh[4], bh[5], bh[6], bh[7], stg + 16384 + bRow + 1024 + bCh);
            LDSM_X4(bl[0], bl[1], bl[2], bl[3], stg + 24576 + bRow + bCh);
            LDSM_X4(bl[4], bl[5], bl[6], bl[7], stg + 24576 + bRow + 1024 + bCh);

#pragma unroll
            for (int mt = 0; mt < 4; mt++)
#pragma unroll
                for (int nt = 0; nt < 4; nt++) {
                    mma16816(acc[mt][nt], ah[mt], &bh[nt * 2]);
                    mma16816(acc[mt][nt], ah[mt], &bl[nt * 2]);
                    mma16816(acc[mt][nt], al[mt], &bh[nt * 2]);
                }
        }

        // issue stage i+2 (readers of that buffer joined at this iter's sync)
        const int nx = i + 2;
        if (nx < nK) {
            const uint32_t st = sm + (uint32_t)(nx % NSTAGE) * STAGE_BYTES;
            cp_tile(st,         Ah, lda, m0, nx, tid);
            cp_tile(st + 8192,  Al, lda, m0, nx, tid);
            cp_tile(st + 16384, Bh, ldb, n0, nx, tid);
            cp_tile(st + 24576, Bl, ldb, n0, nx, tid);
        }
        CP_COMMIT();
    }
    __syncthreads();   // mainloop done; smem reusable below

    // ---- epilogue ----
    const int g  = lane >> 2;
    const int tg = lane & 3;
    float rsum[4][2];
    if (EPI == 3) {
#pragma unroll
        for (int mt = 0; mt < 4; mt++) { rsum[mt][0] = 0.f; rsum[mt][1] = 0.f; }
    }

#pragma unroll
    for (int mt = 0; mt < 4; mt++) {
        const int m = m0 + mW + mt * 16 + g;
        float bm0 = 0.f, bm8 = 0.f;
        if (EPI == 2) { bm0 = bias[m]; bm8 = bias[m + 8]; }
#pragma unroll
        for (int nt = 0; nt < 4; nt++) {
            const int n = n0 + nW + nt * 8 + tg * 2;
            float d0 = acc[mt][nt][0] * alpha;
            float d1 = acc[mt][nt][1] * alpha;
            float d2 = acc[mt][nt][2] * alpha;
            float d3 = acc[mt][nt][3] * alpha;
            if (EPI == 1) {
                float2 bb = *(const float2*)(bias + n);
                d0 += bb.x; d1 += bb.y; d2 += bb.x; d3 += bb.y;
            } else if (EPI == 2) {
                d0 += bm0; d1 += bm0; d2 += bm8; d3 += bm8;
            } else if (EPI == 3) {
                d0 = __expf(d0); d1 = __expf(d1); d2 = __expf(d2); d3 = __expf(d3);
                rsum[mt][0] += d0 + d1;
                rsum[mt][1] += d2 + d3;
            } else if (EPI == 4) {
                float2 iv = *(const float2*)(aux + (size_t)blockIdx.z * Sn + n);
                d0 *= iv.x; d1 *= iv.y; d2 *= iv.x; d3 *= iv.y;
            }
            if (EPI == 4) {
                float* C = (float*)Ch + (size_t)blockIdx.z * sC;
                float2 o0 = { d0, d1 };
                float2 o1 = { d2, d3 };
                *(float2*)(C + (size_t)m * ldc + n)       = o0;
                *(float2*)(C + (size_t)(m + 8) * ldc + n) = o1;
            } else {
                bf16 h0, l0, h1, l1, h2, l2, h3, l3;
                split_hl(d0, h0, l0); split_hl(d1, h1, l1);
                split_hl(d2, h2, l2); split_hl(d3, h3, l3);
                bf16* CH = (bf16*)Ch + (size_t)blockIdx.z * sC;
                bf16* CL = (bf16*)Cl + (size_t)blockIdx.z * sC;
                *(__nv_bfloat162*)(CH + (size_t)m * ldc + n)       = __nv_bfloat162(h0, h1);
                *(__nv_bfloat162*)(CH + (size_t)(m + 8) * ldc + n) = __nv_bfloat162(h2, h3);
                *(__nv_bfloat162*)(CL + (size_t)m * ldc + n)       = __nv_bfloat162(l0, l1);
                *(__nv_bfloat162*)(CL + (size_t)(m + 8) * ldc + n) = __nv_bfloat162(l2, l3);
            }
        }
    }

    if (EPI == 3) {
        // reduce partial row sums: across tg lanes, then across the 4 n-warps
#pragma unroll
        for (int mt = 0; mt < 4; mt++) {
#pragma unroll
            for (int h = 0; h < 2; h++) {
                float s = rsum[mt][h];
                s += __shfl_xor_sync(0xffffffffu, s, 1);
                s += __shfl_xor_sync(0xffffffffu, s, 2);
                rsum[mt][h] = s;
            }
        }
        float* ss = (float*)smem;               // [4 n-warps][128 rows]
        const int nWj = wid & 3;
        if (tg == 0) {
#pragma unroll
            for (int mt = 0; mt < 4; mt++) {
                ss[nWj * 128 + mW + mt * 16 + g]     = rsum[mt][0];
                ss[nWj * 128 + mW + mt * 16 + 8 + g] = rsum[mt][1];
            }
        }
        __syncthreads();
        if (tid < 128) {
            float t = ss[tid] + ss[128 + tid] + ss[256 + tid] + ss[384 + tid];
            aux[((size_t)blockIdx.z * 16 + blockIdx.x) * Sn + m0 + tid] = t;
        }
    }
}

// ---------------- converters --------------------------------------------------
__global__ void __launch_bounds__(256)
xpose_pack(const float* __restrict__ x, bf16* __restrict__ xh, bf16* __restrict__ xl)
{
    __shared__ float t[32][33];
    const int tx = threadIdx.x, ty = threadIdx.y;
    const int s0 = blockIdx.x * 32, c0 = blockIdx.y * 32;
    const size_t bi = (size_t)blockIdx.z * Cin * Sn;
    const size_t bo = (size_t)blockIdx.z * Sn * Cin;
#pragma unroll
    for (int j = ty; j < 32; j += 8)
        t[j][tx] = x[bi + (size_t)(c0 + j) * Sn + s0 + tx];
    __syncthreads();
#pragma unroll
    for (int j = ty; j < 32; j += 8) {
        bf16 h, l;
        split_hl(t[tx][j], h, l);
        xh[bo + (size_t)(s0 + j) * Cin + c0 + tx] = h;
        xl[bo + (size_t)(s0 + j) * Cin + c0 + tx] = l;
    }
}

__global__ void __launch_bounds__(256)
pack_f32(const float* __restrict__ in, bf16* __restrict__ oh, bf16* __restrict__ ol, int n4)
{
    int i = blockIdx.x * 256 + threadIdx.x;
    if (i < n4) {
        float4 v = ((const float4*)in)[i];
        bf16 h0, l0, h1, l1, h2, l2, h3, l3;
        split_hl(v.x, h0, l0); split_hl(v.y, h1, l1);
        split_hl(v.z, h2, l2); split_hl(v.w, h3, l3);
        uint2 ho, lo;
        ho.x = (uint32_t)__bfloat16_as_ushort(h0) | ((uint32_t)__bfloat16_as_ushort(h1) << 16);
        ho.y = (uint32_t)__bfloat16_as_ushort(h2) | ((uint32_t)__bfloat16_as_ushort(h3) << 16);
        lo.x = (uint32_t)__bfloat16_as_ushort(l0) | ((uint32_t)__bfloat16_as_ushort(l1) << 16);
        lo.y = (uint32_t)__bfloat16_as_ushort(l2) | ((uint32_t)__bfloat16_as_ushort(l3) << 16);
        ((uint2*)oh)[i] = ho;
        ((uint2*)ol)[i] = lo;
    }
}

// rowsum over the 16 n-tiles -> reciprocal
__global__ void __launch_bounds__(256)
reduce_inv(const float* __restrict__ psum, float* __restrict__ inv)
{
    int i = blockIdx.x * 256 + threadIdx.x;     // over Bn*Sn
    int b = i >> 11, s = i & 2047;
    const float* p = psum + (size_t)b * 16 * Sn + s;
    float t = 0.f;
#pragma unroll
    for (int j = 0; j < 16; j++) t += p[(size_t)j * Sn];
    inv[i] = 1.0f / t;
}

// -----------------------------------------------------------------------------
extern "C" void kernel_launch(void* const* d_in, const int* in_sizes, int n_in,
                              void* d_out, int out_size)
{
    (void)in_sizes; (void)n_in; (void)out_size;
    const float* x  = (const float*)d_in[0];
    const float* wq = (const float*)d_in[1];
    const float* bq = (const float*)d_in[2];
    const float* wk = (const float*)d_in[3];
    const float* bk = (const float*)d_in[4];
    const float* wv = (const float*)d_in[5];
    const float* bv = (const float*)d_in[6];
    float* out = (float*)d_out;

    bf16 *xh, *xl, *wqkh, *wqkl, *wvh, *wvl, *qkh, *qkl, *vh, *vl, *eh, *el;
    float *bqk, *psum, *inv;
    cudaGetSymbolAddress((void**)&xh,   g_xT_h);  cudaGetSymbolAddress((void**)&xl,   g_xT_l);
    cudaGetSymbolAddress((void**)&wqkh, g_wqk_h); cudaGetSymbolAddress((void**)&wqkl, g_wqk_l);
    cudaGetSymbolAddress((void**)&wvh,  g_wv_h);  cudaGetSymbolAddress((void**)&wvl,  g_wv_l);
    cudaGetSymbolAddress((void**)&bqk,  g_bqk);
    cudaGetSymbolAddress((void**)&qkh,  g_qk_h);  cudaGetSymbolAddress((void**)&qkl,  g_qk_l);
    cudaGetSymbolAddress((void**)&vh,   g_v_h);   cudaGetSymbolAddress((void**)&vl,   g_v_l);
    cudaGetSymbolAddress((void**)&eh,   g_e_h);   cudaGetSymbolAddress((void**)&el,   g_e_l);
    cudaGetSymbolAddress((void**)&psum, g_psum);  cudaGetSymbolAddress((void**)&inv,  g_inv);

    cudaFuncSetAttribute(gemm_mma<1>, cudaFuncAttributeMaxDynamicSharedMemorySize, SM_TOTAL);
    cudaFuncSetAttribute(gemm_mma<2>, cudaFuncAttributeMaxDynamicSharedMemorySize, SM_TOTAL);
    cudaFuncSetAttribute(gemm_mma<3>, cudaFuncAttributeMaxDynamicSharedMemorySize, SM_TOTAL);
    cudaFuncSetAttribute(gemm_mma<4>, cudaFuncAttributeMaxDynamicSharedMemorySize, SM_TOTAL);

    // ---- conversions ----
    xpose_pack<<<dim3(Sn / 32, Cin / 32, Bn), dim3(32, 8)>>>(x, xh, xl);
    pack_f32<<<(KD * Cin / 4 + 255) / 256, 256>>>(wq, wqkh, wqkl, KD * Cin / 4);
    pack_f32<<<(KD * Cin / 4 + 255) / 256, 256>>>(wk, wqkh + (size_t)KD * Cin,
                                                  wqkl + (size_t)KD * Cin, KD * Cin / 4);
    pack_f32<<<(OD * Cin / 4 + 255) / 256, 256>>>(wv, wvh, wvl, OD * Cin / 4);
    cudaMemcpyAsync(bqk,      bq, KD * sizeof(float), cudaMemcpyDeviceToDevice, 0);
    cudaMemcpyAsync(bqk + KD, bk, KD * sizeof(float), cudaMemcpyDeviceToDevice, 0);

    const size_t sxT = (size_t)Sn * Cin;
    const size_t sqk = (size_t)Sn * QKN;
    const size_t sv  = (size_t)OD * Sn;
    const size_t ssc = (size_t)Sn * Sn;

    // qk = xT @ [Wq|Wk]^T + [bq|bk] -> (B,S,1024)   [m=s, n=qk-ch, k=c]
    gemm_mma<1><<<dim3(QKN / 128, Sn / 128, Bn), 256, SM_TOTAL>>>(
        xh, xl, wqkh, wqkl, bqk, nullptr, qkh, qkl,
        Cin, Cin, QKN, Cin / 32, sxT, 0, sqk, 1.0f);

    // v = Wv @ x + bv -> (B,OD,S)   [m=o, n=s, k=c]
    gemm_mma<2><<<dim3(Sn / 128, OD / 128, Bn), 256, SM_TOTAL>>>(
        wvh, wvl, xh, xl, bv, nullptr, vh, vl,
        Cin, Cin, Sn, Cin / 32, 0, sxT, sv, 1.0f);

    // E = exp(q @ k^T / sqrt(KD)) -> planes + partial row sums   [m=s, n=t, k=kd]
    gemm_mma<3><<<dim3(Sn / 128, Sn / 128, Bn), 256, SM_TOTAL>>>(
        qkh, qkl, qkh + KD, qkl + KD, nullptr, psum, eh, el,
        QKN, QKN, Sn, KD / 32, sqk, sqk, ssc, 0.04419417382415922f);

    // inv rowsums
    reduce_inv<<<Bn * Sn / 256, 256>>>(psum, inv);

    // out = (v @ E^T) * inv[s] -> (B,OD,S) fp32 into d_out   [m=o, n=s, k=t]
    gemm_mma<4><<<dim3(Sn / 128, OD / 128, Bn), 256, SM_TOTAL>>>(
        vh, vl, eh, el, nullptr, inv, out, nullptr,
        Sn, Sn, Sn, Sn / 32, sv, ssc, sv, 1.0f);
}